// round 1
// baseline (speedup 1.0000x reference)
#include <cuda_runtime.h>
#include <cuda_bf16.h>

// Problem constants (fixed by the reference: B=8, T=2048, D=2048)
#define B_SZ 8
#define T_SZ 2048
#define D_SZ 2048
#define M_SZ (B_SZ * T_SZ)   // 16384 rows

// Scratch for the three GEMM outputs (device globals: no runtime allocation).
__device__ float g_k[(size_t)M_SZ * D_SZ];
__device__ float g_v[(size_t)M_SZ * D_SZ];
__device__ float g_r[(size_t)M_SZ * D_SZ];

// ---------------------------------------------------------------------------
// GEMM: C[m,n] = sum_d A[m,d] * W[n,d]   (both operands K-contiguous, row-major)
//   z = 0: C = g_k, W = Wk, A = time-shifted x
//   z = 1: C = g_v, W = Wv, A = time-shifted x
//   z = 2: C = g_r, W = Wr, A = x
// Time shift: row m -> (b = m/T, t = m%T); source row = m-1 if t>0 else zeros.
// Block tile 128x128, K-tile 16, 256 threads, 8x8 register micro-tile.
// ---------------------------------------------------------------------------
__global__ __launch_bounds__(256, 2)
void gemm3_kernel(const float* __restrict__ x,
                  const float* __restrict__ Wk,
                  const float* __restrict__ Wv,
                  const float* __restrict__ Wr)
{
    const int z = blockIdx.z;
    const float* __restrict__ W = (z == 0) ? Wk : (z == 1) ? Wv : Wr;
    float* __restrict__ C = (z == 0) ? g_k : (z == 1) ? g_v : g_r;
    const bool shift = (z < 2);

    __shared__ float As[16][128];
    __shared__ float Ws[16][128];

    const int tid = threadIdx.x;
    const int tx = tid & 15;        // 0..15 -> n micro-tile
    const int ty = tid >> 4;        // 0..15 -> m micro-tile
    const int m0 = blockIdx.y * 128;
    const int n0 = blockIdx.x * 128;

    float acc[8][8];
#pragma unroll
    for (int i = 0; i < 8; i++)
#pragma unroll
        for (int j = 0; j < 8; j++) acc[i][j] = 0.f;

    for (int kt = 0; kt < D_SZ; kt += 16) {
        // Each thread loads 2 float4 per operand. slot = tid*2+j over 512 slots.
#pragma unroll
        for (int j = 0; j < 2; j++) {
            const int slot = tid * 2 + j;
            const int row  = slot >> 2;        // 0..127
            const int kq   = (slot & 3) * 4;   // 0,4,8,12

            // --- A tile (with optional time shift) ---
            const int gm = m0 + row;
            float4 av = make_float4(0.f, 0.f, 0.f, 0.f);
            bool valid = true;
            int srow = gm;
            if (shift) {
                if ((gm & (T_SZ - 1)) == 0) valid = false;  // t == 0 -> zero row
                else srow = gm - 1;
            }
            if (valid)
                av = *(const float4*)(x + (size_t)srow * D_SZ + kt + kq);
            As[kq + 0][row] = av.x;
            As[kq + 1][row] = av.y;
            As[kq + 2][row] = av.z;
            As[kq + 3][row] = av.w;

            // --- W tile ---
            const int gn = n0 + row;
            const float4 wv = *(const float4*)(W + (size_t)gn * D_SZ + kt + kq);
            Ws[kq + 0][row] = wv.x;
            Ws[kq + 1][row] = wv.y;
            Ws[kq + 2][row] = wv.z;
            Ws[kq + 3][row] = wv.w;
        }
        __syncthreads();

#pragma unroll
        for (int kk = 0; kk < 16; kk++) {
            float a[8], bb[8];
            *(float4*)&a[0]  = *(const float4*)&As[kk][ty * 8];
            *(float4*)&a[4]  = *(const float4*)&As[kk][ty * 8 + 4];
            *(float4*)&bb[0] = *(const float4*)&Ws[kk][tx * 8];
            *(float4*)&bb[4] = *(const float4*)&Ws[kk][tx * 8 + 4];
#pragma unroll
            for (int i = 0; i < 8; i++)
#pragma unroll
                for (int j = 0; j < 8; j++)
                    acc[i][j] = fmaf(a[i], bb[j], acc[i][j]);
        }
        __syncthreads();
    }

    // Write back
#pragma unroll
    for (int i = 0; i < 8; i++) {
        const int gm = m0 + ty * 8 + i;
        float* cp = C + (size_t)gm * D_SZ + n0 + tx * 8;
        *(float4*)cp       = *(float4*)&acc[i][0];
        *(float4*)(cp + 4) = *(float4*)&acc[i][4];
    }
}

// ---------------------------------------------------------------------------
// Fused WKV scan + epilogue + second output.
// One thread per channel (b,d); sequential over T with unroll-8 load batching
// so 24 LDGs are in flight before the dependent recurrence math.
//   num_t = w*num_{t-1} + exp(k_t)*v_t ;  den_t = w*den_{t-1} + exp(k_t)
//   out[b,t,d] = r_t * num_t / (den_t + 1e-8)
// Also writes out2[b,d] = x[b, T-2, d]  (== shifted[:, -1]).
// ---------------------------------------------------------------------------
__global__ void wkv_scan_kernel(const float* __restrict__ time_decay,
                                const float* __restrict__ x,
                                float* __restrict__ out)
{
    const int c = blockIdx.x * blockDim.x + threadIdx.x;
    if (c >= B_SZ * D_SZ) return;
    const int b = c / D_SZ;
    const int d = c % D_SZ;

    const float w = expf(-expf(time_decay[d]));

    const size_t base = (size_t)b * T_SZ * D_SZ + d;
    const float* kp = g_k + base;
    const float* vp = g_v + base;
    const float* rp = g_r + base;
    float* op = out + base;

    float num = 0.f, den = 0.f;

    for (int t = 0; t < T_SZ; t += 8) {
        float kk[8], vv[8], rr[8];
#pragma unroll
        for (int i = 0; i < 8; i++) {
            const size_t o = (size_t)(t + i) * D_SZ;
            kk[i] = kp[o];
            vv[i] = vp[o];
            rr[i] = rp[o];
        }
#pragma unroll
        for (int i = 0; i < 8; i++) {
            const float ek = expf(kk[i]);
            num = fmaf(w, num, ek * vv[i]);
            den = fmaf(w, den, ek);
            op[(size_t)(t + i) * D_SZ] = rr[i] * num / (den + 1e-8f);
        }
    }

    // Second output: shifted[:, -1] = x[:, T-2, :]
    float* out2 = out + (size_t)B_SZ * T_SZ * D_SZ;
    out2[c] = x[(size_t)b * T_SZ * D_SZ + (size_t)(T_SZ - 2) * D_SZ + d];
}

extern "C" void kernel_launch(void* const* d_in, const int* in_sizes, int n_in,
                              void* d_out, int out_size)
{
    const float* x  = (const float*)d_in[0];
    const float* Wk = (const float*)d_in[1];
    const float* Wv = (const float*)d_in[2];
    const float* Wr = (const float*)d_in[3];
    const float* td = (const float*)d_in[4];
    float* out = (float*)d_out;

    dim3 ggrid(D_SZ / 128, M_SZ / 128, 3);   // (16, 128, 3)
    gemm3_kernel<<<ggrid, 256>>>(x, Wk, Wv, Wr);

    const int chans = B_SZ * D_SZ;           // 16384
    wkv_scan_kernel<<<chans / 128, 128>>>(td, x, out);
}

// round 3
// speedup vs baseline: 3.2093x; 3.2093x over previous
#include <cuda_runtime.h>
#include <cuda_bf16.h>
#include <cstdint>

// Problem constants (fixed: B=8, T=2048, D=2048)
#define B_SZ 8
#define T_SZ 2048
#define D_SZ 2048
#define M_SZ (B_SZ * T_SZ)        // 16384
#define CH_SZ (B_SZ * D_SZ)       // 16384 channels
#define SEG_LEN 256
#define N_SEG (T_SZ / SEG_LEN)    // 8

// ---------------- device scratch (static: no runtime allocation) ------------
__device__ __nv_bfloat16 g_xs_hi[(size_t)M_SZ * D_SZ];
__device__ __nv_bfloat16 g_xs_lo[(size_t)M_SZ * D_SZ];
__device__ __nv_bfloat16 g_xr_hi[(size_t)M_SZ * D_SZ];
__device__ __nv_bfloat16 g_xr_lo[(size_t)M_SZ * D_SZ];
__device__ __nv_bfloat16 g_w_hi[(size_t)3 * D_SZ * D_SZ];
__device__ __nv_bfloat16 g_w_lo[(size_t)3 * D_SZ * D_SZ];
__device__ float g_k[(size_t)M_SZ * D_SZ];
__device__ float g_v[(size_t)M_SZ * D_SZ];
__device__ float g_r[(size_t)M_SZ * D_SZ];
__device__ float g_cn[(size_t)N_SEG * CH_SZ];
__device__ float g_cd[(size_t)N_SEG * CH_SZ];

// ---------------- helpers -----------------------------------------------------
__device__ __forceinline__ uint32_t smem_u32(const void* p) {
    uint32_t a;
    asm("{ .reg .u64 t; cvta.to.shared.u64 t, %1; cvt.u32.u64 %0, t; }" : "=r"(a) : "l"(p));
    return a;
}
__device__ __forceinline__ void cp16(uint32_t dst, const void* src) {
    asm volatile("cp.async.cg.shared.global [%0], [%1], 16;" :: "r"(dst), "l"(src));
}
#define SWZ128(o) ((o) ^ (((o) >> 3) & 0x70))

__device__ __forceinline__ void ldsm_x4(uint32_t* r, uint32_t addr) {
    asm volatile("ldmatrix.sync.aligned.m8n8.x4.shared.b16 {%0,%1,%2,%3}, [%4];"
                 : "=r"(r[0]), "=r"(r[1]), "=r"(r[2]), "=r"(r[3]) : "r"(addr));
}
__device__ __forceinline__ void mma16816(float* c, const uint32_t* a, const uint32_t* b) {
    asm volatile(
        "mma.sync.aligned.m16n8k16.row.col.f32.bf16.bf16.f32 "
        "{%0,%1,%2,%3}, {%4,%5,%6,%7}, {%8,%9}, {%0,%1,%2,%3};"
        : "+f"(c[0]), "+f"(c[1]), "+f"(c[2]), "+f"(c[3])
        : "r"(a[0]), "r"(a[1]), "r"(a[2]), "r"(a[3]), "r"(b[0]), "r"(b[1]));
}

// ---------------- conversion: fp32 -> bf16 hi/lo -------------------------------
__device__ __forceinline__ void split_store(__nv_bfloat16* hi, __nv_bfloat16* lo,
                                            size_t i, float a) {
    __nv_bfloat16 h = __float2bfloat16_rn(a);
    hi[i] = h;
    lo[i] = __float2bfloat16_rn(a - __bfloat162float(h));
}

__global__ void convert_x_kernel(const float* __restrict__ x) {
    size_t i4 = (size_t)blockIdx.x * blockDim.x + threadIdx.x;
    if (i4 >= (size_t)M_SZ * D_SZ / 4) return;
    size_t i = i4 * 4;
    float4 v = *(const float4*)(x + i);
    split_store(g_xr_hi, g_xr_lo, i + 0, v.x);
    split_store(g_xr_hi, g_xr_lo, i + 1, v.y);
    split_store(g_xr_hi, g_xr_lo, i + 2, v.z);
    split_store(g_xr_hi, g_xr_lo, i + 3, v.w);
    size_t m = i / D_SZ;
    float4 s = make_float4(0.f, 0.f, 0.f, 0.f);
    if ((m & (T_SZ - 1)) != 0) s = *(const float4*)(x + i - D_SZ);
    split_store(g_xs_hi, g_xs_lo, i + 0, s.x);
    split_store(g_xs_hi, g_xs_lo, i + 1, s.y);
    split_store(g_xs_hi, g_xs_lo, i + 2, s.z);
    split_store(g_xs_hi, g_xs_lo, i + 3, s.w);
}

__global__ void convert_w_kernel(const float* __restrict__ Wk,
                                 const float* __restrict__ Wv,
                                 const float* __restrict__ Wr) {
    const int z = blockIdx.y;
    const float* W = (z == 0) ? Wk : (z == 1) ? Wv : Wr;
    size_t i4 = (size_t)blockIdx.x * blockDim.x + threadIdx.x;
    if (i4 >= (size_t)D_SZ * D_SZ / 4) return;
    size_t i = i4 * 4;
    size_t o = (size_t)z * D_SZ * D_SZ + i;
    float4 v = *(const float4*)(W + i);
    split_store(g_w_hi, g_w_lo, o + 0, v.x);
    split_store(g_w_hi, g_w_lo, o + 1, v.y);
    split_store(g_w_hi, g_w_lo, o + 2, v.z);
    split_store(g_w_hi, g_w_lo, o + 3, v.w);
}

// ---------------- HMMA GEMM: C[m,n] = sum_k A[m,k]*W[n,k] ---------------------
// bf16 split: hi*hi + hi*lo + lo*hi. Tile 128x128, BK=64 elems (128B SW128 rows),
// 256 threads = 8 warps (2 x 4), warp tile 64x32, m16n8k16, 2-stage cp.async.
#define BM 128
#define BN 128
#define BK 64
#define N_CHUNK (D_SZ / BK)        // 32
#define TILE_B 16384               // one 128x64 bf16 tile, 128B rows
#define STAGE_BYTES (4 * TILE_B)   // A_hi A_lo B_hi B_lo
#define GEMM_SMEM (2 * STAGE_BYTES)

__global__ __launch_bounds__(256, 1)
void gemm_hmma_kernel() {
    extern __shared__ char smem[];
    const uint32_t sbase = smem_u32(smem);
    const int tid = threadIdx.x;
    const int wid = tid >> 5;
    const int lane = tid & 31;
    const int wm = wid & 1;          // 2 warps over M
    const int wn = wid >> 1;         // 4 warps over N

    const int z = blockIdx.z;
    const int m0 = blockIdx.y * BM;
    const int n0 = blockIdx.x * BN;

    const __nv_bfloat16* A_hi = (z < 2) ? g_xs_hi : g_xr_hi;
    const __nv_bfloat16* A_lo = (z < 2) ? g_xs_lo : g_xr_lo;
    const __nv_bfloat16* B_hi = g_w_hi + (size_t)z * D_SZ * D_SZ;
    const __nv_bfloat16* B_lo = g_w_lo + (size_t)z * D_SZ * D_SZ;
    float* C = (z == 0) ? g_k : (z == 1) ? g_v : g_r;

    float acc[4][4][4];
#pragma unroll
    for (int i = 0; i < 4; i++)
#pragma unroll
        for (int j = 0; j < 4; j++)
#pragma unroll
            for (int q = 0; q < 4; q++) acc[i][j][q] = 0.f;

    // stage loader: K-chunk c into stage s (each of 4 tiles: 1024 16B lines)
    auto load_stage = [&](int c, int s) {
        const int kt = c * BK;
        const uint32_t st = sbase + s * STAGE_BYTES;
#pragma unroll
        for (int it = 0; it < 4; it++) {
            const int i = tid + it * 256;
            const int row = i >> 3, seg = i & 7;
            const uint32_t sw = SWZ128((uint32_t)(row * 128 + seg * 16));
            const size_t ga = (size_t)(m0 + row) * D_SZ + kt + seg * 8;
            const size_t gb = (size_t)(n0 + row) * D_SZ + kt + seg * 8;
            cp16(st + sw,              A_hi + ga);
            cp16(st + TILE_B + sw,     A_lo + ga);
            cp16(st + 2 * TILE_B + sw, B_hi + gb);
            cp16(st + 3 * TILE_B + sw, B_lo + gb);
        }
        asm volatile("cp.async.commit_group;" ::: "memory");
    };

    load_stage(0, 0);
    load_stage(1, 1);

    // per-lane ldmatrix address offsets (within a tile)
    const int a_row = lane & 15;          // row within 16
    const int a_half = lane >> 4;         // 16B half
    const int b_nr = (lane & 7) + ((lane >> 4) << 3);
    const int b_half = (lane >> 3) & 1;

    for (int c = 0; c < N_CHUNK; c++) {
        const int s = c & 1;
        if (c == N_CHUNK - 1) asm volatile("cp.async.wait_group 0;" ::: "memory");
        else                  asm volatile("cp.async.wait_group 1;" ::: "memory");
        __syncthreads();

        const uint32_t sA_hi = sbase + s * STAGE_BYTES;
        const uint32_t sA_lo = sA_hi + TILE_B;
        const uint32_t sB_hi = sA_hi + 2 * TILE_B;
        const uint32_t sB_lo = sA_hi + 3 * TILE_B;

#pragma unroll
        for (int ks = 0; ks < 4; ks++) {
            uint32_t ah[4][4], al[4][4], bh[2][4], bl[2][4];
#pragma unroll
            for (int mi = 0; mi < 4; mi++) {
                const uint32_t off = SWZ128(
                    (uint32_t)((wm * 64 + mi * 16 + a_row) * 128 + ks * 32 + a_half * 16));
                ldsm_x4(ah[mi], sA_hi + off);
                ldsm_x4(al[mi], sA_lo + off);
            }
#pragma unroll
            for (int j = 0; j < 2; j++) {
                const uint32_t off = SWZ128(
                    (uint32_t)((wn * 32 + j * 16 + b_nr) * 128 + ks * 32 + b_half * 16));
                ldsm_x4(bh[j], sB_hi + off);
                ldsm_x4(bl[j], sB_lo + off);
            }
#pragma unroll
            for (int mi = 0; mi < 4; mi++)
#pragma unroll
                for (int ni = 0; ni < 4; ni++) {
                    const uint32_t* Bh = &bh[ni >> 1][(ni & 1) * 2];
                    const uint32_t* Bl = &bl[ni >> 1][(ni & 1) * 2];
                    mma16816(acc[mi][ni], ah[mi], Bh);   // hi*hi
                    mma16816(acc[mi][ni], ah[mi], Bl);   // hi*lo
                    mma16816(acc[mi][ni], al[mi], Bh);   // lo*hi
                }
        }
        __syncthreads();   // all warps done reading stage s
        if (c + 2 < N_CHUNK) load_stage(c + 2, s);
    }

    // epilogue: thread t of tile holds (row=t/4, col=(t%4)*2) and row+8
#pragma unroll
    for (int mi = 0; mi < 4; mi++) {
        const int gm = m0 + wm * 64 + mi * 16 + (lane >> 2);
#pragma unroll
        for (int ni = 0; ni < 4; ni++) {
            const int gn = n0 + wn * 32 + ni * 8 + (lane & 3) * 2;
            float* p0 = C + (size_t)gm * D_SZ + gn;
            float* p1 = p0 + 8 * D_SZ;
            *(float2*)p0 = make_float2(acc[mi][ni][0], acc[mi][ni][1]);
            *(float2*)p1 = make_float2(acc[mi][ni][2], acc[mi][ni][3]);
        }
    }
}

// ---------------- split WKV scan ------------------------------------------------
__global__ void wkv_p1_kernel(const float* __restrict__ time_decay) {
    const int gid = blockIdx.x * blockDim.x + threadIdx.x;
    const int c = gid & (CH_SZ - 1);
    const int seg = gid >> 14;
    const int d = c & (D_SZ - 1);
    const int b = c >> 11;
    const float w = expf(-expf(time_decay[d]));

    const size_t base = (size_t)b * T_SZ * D_SZ + (size_t)seg * SEG_LEN * D_SZ + d;
    const float* kp = g_k + base;
    const float* vp = g_v + base;

    float num = 0.f, den = 0.f;
    for (int t = 0; t < SEG_LEN; t += 8) {
        float kk[8], vv[8];
#pragma unroll
        for (int i = 0; i < 8; i++) {
            const size_t o = (size_t)(t + i) * D_SZ;
            kk[i] = kp[o]; vv[i] = vp[o];
        }
#pragma unroll
        for (int i = 0; i < 8; i++) {
            const float ek = expf(kk[i]);
            num = fmaf(w, num, ek * vv[i]);
            den = fmaf(w, den, ek);
        }
    }
    g_cn[gid] = num;
    g_cd[gid] = den;
}

__global__ void wkv_p2_kernel(const float* __restrict__ time_decay,
                              const float* __restrict__ x,
                              float* __restrict__ out) {
    const int gid = blockIdx.x * blockDim.x + threadIdx.x;
    const int c = gid & (CH_SZ - 1);
    const int seg = gid >> 14;
    const int d = c & (D_SZ - 1);
    const int b = c >> 11;

    const float e = expf(time_decay[d]);
    const float w = expf(-e);
    const float wl = expf(-(float)SEG_LEN * e);   // w^SEG_LEN

    float num = 0.f, den = 0.f;
    for (int i = 0; i < seg; i++) {
        num = fmaf(wl, num, g_cn[i * CH_SZ + c]);
        den = fmaf(wl, den, g_cd[i * CH_SZ + c]);
    }

    const size_t base = (size_t)b * T_SZ * D_SZ + (size_t)seg * SEG_LEN * D_SZ + d;
    const float* kp = g_k + base;
    const float* vp = g_v + base;
    const float* rp = g_r + base;
    float* op = out + base;

    for (int t = 0; t < SEG_LEN; t += 8) {
        float kk[8], vv[8], rr[8];
#pragma unroll
        for (int i = 0; i < 8; i++) {
            const size_t o = (size_t)(t + i) * D_SZ;
            kk[i] = kp[o]; vv[i] = vp[o]; rr[i] = rp[o];
        }
#pragma unroll
        for (int i = 0; i < 8; i++) {
            const float ek = expf(kk[i]);
            num = fmaf(w, num, ek * vv[i]);
            den = fmaf(w, den, ek);
            op[(size_t)(t + i) * D_SZ] = rr[i] * num / (den + 1e-8f);
        }
    }

    if (seg == 0) {
        float* out2 = out + (size_t)B_SZ * T_SZ * D_SZ;
        out2[c] = x[(size_t)b * T_SZ * D_SZ + (size_t)(T_SZ - 2) * D_SZ + d];
    }
}

// ---------------- launch --------------------------------------------------------
extern "C" void kernel_launch(void* const* d_in, const int* in_sizes, int n_in,
                              void* d_out, int out_size)
{
    const float* x  = (const float*)d_in[0];
    const float* Wk = (const float*)d_in[1];
    const float* Wv = (const float*)d_in[2];
    const float* Wr = (const float*)d_in[3];
    const float* td = (const float*)d_in[4];
    float* out = (float*)d_out;

    cudaFuncSetAttribute(gemm_hmma_kernel,
                         cudaFuncAttributeMaxDynamicSharedMemorySize, GEMM_SMEM);

    convert_x_kernel<<<(M_SZ * (size_t)D_SZ / 4 + 255) / 256, 256>>>(x);
    {
        dim3 g((D_SZ * (size_t)D_SZ / 4 + 255) / 256, 3);
        convert_w_kernel<<<g, 256>>>(Wk, Wv, Wr);
    }

    dim3 gg(D_SZ / BN, M_SZ / BM, 3);   // (16, 128, 3)
    gemm_hmma_kernel<<<gg, 256, GEMM_SMEM>>>();

    const int total = N_SEG * CH_SZ;    // 131072
    wkv_p1_kernel<<<total / 256, 256>>>(td);
    wkv_p2_kernel<<<total / 256, 256>>>(td, x, out);
}

// round 4
// speedup vs baseline: 5.0796x; 1.5828x over previous
#include <cuda_runtime.h>
#include <cuda_fp16.h>
#include <cuda_bf16.h>
#include <cstdint>

// Problem constants (fixed: B=8, T=2048, D=2048)
#define B_SZ 8
#define T_SZ 2048
#define D_SZ 2048
#define M_SZ (B_SZ * T_SZ)        // 16384
#define CH_SZ (B_SZ * D_SZ)       // 16384 channels
#define SEG_LEN 256
#define N_SEG (T_SZ / SEG_LEN)    // 8

// ---------------- device scratch (static: no runtime allocation) ------------
__device__ __half g_x_hi[(size_t)M_SZ * D_SZ];   // fp16(x)
__device__ __half g_x_lo[(size_t)M_SZ * D_SZ];   // fp16(x - hi)
__device__ __half g_wh[(size_t)3 * D_SZ * D_SZ]; // fp16(W) for Wk,Wv,Wr
__device__ float g_k[(size_t)M_SZ * D_SZ];
__device__ float g_v[(size_t)M_SZ * D_SZ];
__device__ float g_r[(size_t)M_SZ * D_SZ];
__device__ float g_cn[(size_t)N_SEG * CH_SZ];
__device__ float g_cd[(size_t)N_SEG * CH_SZ];

// ---------------- helpers -----------------------------------------------------
__device__ __forceinline__ uint32_t smem_u32(const void* p) {
    uint32_t a;
    asm("{ .reg .u64 t; cvta.to.shared.u64 t, %1; cvt.u32.u64 %0, t; }" : "=r"(a) : "l"(p));
    return a;
}
__device__ __forceinline__ void cp16(uint32_t dst, const void* src) {
    asm volatile("cp.async.cg.shared.global [%0], [%1], 16;" :: "r"(dst), "l"(src));
}
// zfill variant: src_sz = 0 -> write 16 zero bytes (no memory access of src)
__device__ __forceinline__ void cp16z(uint32_t dst, const void* src, uint32_t src_sz) {
    asm volatile("cp.async.cg.shared.global [%0], [%1], 16, %2;"
                 :: "r"(dst), "l"(src), "r"(src_sz));
}
#define SWZ128(o) ((o) ^ (((o) >> 3) & 0x70))

__device__ __forceinline__ void ldsm_x4(uint32_t* r, uint32_t addr) {
    asm volatile("ldmatrix.sync.aligned.m8n8.x4.shared.b16 {%0,%1,%2,%3}, [%4];"
                 : "=r"(r[0]), "=r"(r[1]), "=r"(r[2]), "=r"(r[3]) : "r"(addr));
}
__device__ __forceinline__ void mma16816(float* c, const uint32_t* a, const uint32_t* b) {
    asm volatile(
        "mma.sync.aligned.m16n8k16.row.col.f32.f16.f16.f32 "
        "{%0,%1,%2,%3}, {%4,%5,%6,%7}, {%8,%9}, {%0,%1,%2,%3};"
        : "+f"(c[0]), "+f"(c[1]), "+f"(c[2]), "+f"(c[3])
        : "r"(a[0]), "r"(a[1]), "r"(a[2]), "r"(a[3]), "r"(b[0]), "r"(b[1]));
}

// ---------------- conversion: fp32 -> fp16 hi/lo -------------------------------
__global__ void convert_x_kernel(const float* __restrict__ x) {
    size_t i4 = (size_t)blockIdx.x * blockDim.x + threadIdx.x;
    if (i4 >= (size_t)M_SZ * D_SZ / 4) return;
    size_t i = i4 * 4;
    float4 v = *(const float4*)(x + i);
    __half h0 = __float2half_rn(v.x);
    __half h1 = __float2half_rn(v.y);
    __half h2 = __float2half_rn(v.z);
    __half h3 = __float2half_rn(v.w);
    __half2* hp = (__half2*)(g_x_hi + i);
    hp[0] = __halves2half2(h0, h1);
    hp[1] = __halves2half2(h2, h3);
    __half2* lp = (__half2*)(g_x_lo + i);
    lp[0] = __halves2half2(__float2half_rn(v.x - __half2float(h0)),
                           __float2half_rn(v.y - __half2float(h1)));
    lp[1] = __halves2half2(__float2half_rn(v.z - __half2float(h2)),
                           __float2half_rn(v.w - __half2float(h3)));
}

__global__ void convert_w_kernel(const float* __restrict__ Wk,
                                 const float* __restrict__ Wv,
                                 const float* __restrict__ Wr) {
    const int z = blockIdx.y;
    const float* W = (z == 0) ? Wk : (z == 1) ? Wv : Wr;
    size_t i4 = (size_t)blockIdx.x * blockDim.x + threadIdx.x;
    if (i4 >= (size_t)D_SZ * D_SZ / 4) return;
    size_t i = i4 * 4;
    float4 v = *(const float4*)(W + i);
    __half2* op = (__half2*)(g_wh + (size_t)z * D_SZ * D_SZ + i);
    op[0] = __halves2half2(__float2half_rn(v.x), __float2half_rn(v.y));
    op[1] = __halves2half2(__float2half_rn(v.z), __float2half_rn(v.w));
}

// ---------------- HMMA GEMM: C[m,n] = sum_k A[m,k]*W[n,k] ---------------------
// fp16 asymmetric split: C = A_hi*W + A_lo*W (2 MMAs). Time shift handled by
// reading row m-1 (zfill at t==0). Tile 128x128, BK=64, 2-stage, 2 CTA/SM.
#define BM 128
#define BN 128
#define BK 64
#define N_CHUNK (D_SZ / BK)        // 32
#define TILE_B 16384               // 128 rows x 128B
#define STAGE_BYTES (3 * TILE_B)   // A_hi, A_lo, B
#define GEMM_SMEM (2 * STAGE_BYTES)

__global__ __launch_bounds__(256, 2)
void gemm_hmma_kernel() {
    extern __shared__ char smem[];
    const uint32_t sbase = smem_u32(smem);
    const int tid = threadIdx.x;
    const int wid = tid >> 5;
    const int lane = tid & 31;
    const int wm = wid & 1;          // 2 warps over M
    const int wn = wid >> 1;         // 4 warps over N

    const int z = blockIdx.z;
    const int m0 = blockIdx.y * BM;
    const int n0 = blockIdx.x * BN;
    const bool shift = (z < 2);

    const __half* B_h = g_wh + (size_t)z * D_SZ * D_SZ;
    float* C = (z == 0) ? g_k : (z == 1) ? g_v : g_r;

    float acc[4][4][4];
#pragma unroll
    for (int i = 0; i < 4; i++)
#pragma unroll
        for (int j = 0; j < 4; j++)
#pragma unroll
            for (int q = 0; q < 4; q++) acc[i][j][q] = 0.f;

    // stage loader: K-chunk c into stage s
    auto load_stage = [&](int c, int s) {
        const int kt = c * BK;
        const uint32_t st = sbase + s * STAGE_BYTES;
#pragma unroll
        for (int it = 0; it < 4; it++) {
            const int i = tid + it * 256;
            const int row = i >> 3, seg = i & 7;
            const uint32_t sw = SWZ128((uint32_t)(row * 128 + seg * 16));
            // A (with optional time shift; zero-fill at t==0)
            const int rm = m0 + row;
            uint32_t sz = 16;
            int srow = rm;
            if (shift) {
                if ((rm & (T_SZ - 1)) == 0) { sz = 0; }
                else srow = rm - 1;
            }
            const size_t ga = (size_t)srow * D_SZ + kt + seg * 8;
            cp16z(st + sw,          g_x_hi + ga, sz);
            cp16z(st + TILE_B + sw, g_x_lo + ga, sz);
            // B
            const size_t gb = (size_t)(n0 + row) * D_SZ + kt + seg * 8;
            cp16(st + 2 * TILE_B + sw, B_h + gb);
        }
        asm volatile("cp.async.commit_group;" ::: "memory");
    };

    load_stage(0, 0);
    load_stage(1, 1);

    const int a_row = lane & 15;
    const int a_half = lane >> 4;
    const int b_nr = (lane & 7) + ((lane >> 4) << 3);
    const int b_half = (lane >> 3) & 1;

    for (int c = 0; c < N_CHUNK; c++) {
        const int s = c & 1;
        if (c == N_CHUNK - 1) asm volatile("cp.async.wait_group 0;" ::: "memory");
        else                  asm volatile("cp.async.wait_group 1;" ::: "memory");
        __syncthreads();

        const uint32_t sA_hi = sbase + s * STAGE_BYTES;
        const uint32_t sA_lo = sA_hi + TILE_B;
        const uint32_t sB    = sA_hi + 2 * TILE_B;

#pragma unroll
        for (int ks = 0; ks < 4; ks++) {
            uint32_t ah[4][4], al[4][4], bb[2][4];
#pragma unroll
            for (int mi = 0; mi < 4; mi++) {
                const uint32_t off = SWZ128(
                    (uint32_t)((wm * 64 + mi * 16 + a_row) * 128 + ks * 32 + a_half * 16));
                ldsm_x4(ah[mi], sA_hi + off);
                ldsm_x4(al[mi], sA_lo + off);
            }
#pragma unroll
            for (int j = 0; j < 2; j++) {
                const uint32_t off = SWZ128(
                    (uint32_t)((wn * 32 + j * 16 + b_nr) * 128 + ks * 32 + b_half * 16));
                ldsm_x4(bb[j], sB + off);
            }
#pragma unroll
            for (int mi = 0; mi < 4; mi++)
#pragma unroll
                for (int ni = 0; ni < 4; ni++) {
                    const uint32_t* Bp = &bb[ni >> 1][(ni & 1) * 2];
                    mma16816(acc[mi][ni], ah[mi], Bp);   // hi * W
                    mma16816(acc[mi][ni], al[mi], Bp);   // lo * W
                }
        }
        __syncthreads();
        if (c + 2 < N_CHUNK) load_stage(c + 2, s);
    }

    // epilogue
#pragma unroll
    for (int mi = 0; mi < 4; mi++) {
        const int gm = m0 + wm * 64 + mi * 16 + (lane >> 2);
#pragma unroll
        for (int ni = 0; ni < 4; ni++) {
            const int gn = n0 + wn * 32 + ni * 8 + (lane & 3) * 2;
            float* p0 = C + (size_t)gm * D_SZ + gn;
            float* p1 = p0 + 8 * D_SZ;
            *(float2*)p0 = make_float2(acc[mi][ni][0], acc[mi][ni][1]);
            *(float2*)p1 = make_float2(acc[mi][ni][2], acc[mi][ni][3]);
        }
    }
}

// ---------------- split WKV scan ------------------------------------------------
__global__ void wkv_p1_kernel(const float* __restrict__ time_decay) {
    const int gid = blockIdx.x * blockDim.x + threadIdx.x;
    const int c = gid & (CH_SZ - 1);
    const int seg = gid >> 14;
    const int d = c & (D_SZ - 1);
    const int b = c >> 11;
    const float w = expf(-expf(time_decay[d]));

    const size_t base = (size_t)b * T_SZ * D_SZ + (size_t)seg * SEG_LEN * D_SZ + d;
    const float* kp = g_k + base;
    const float* vp = g_v + base;

    float num = 0.f, den = 0.f;
    for (int t = 0; t < SEG_LEN; t += 8) {
        float kk[8], vv[8];
#pragma unroll
        for (int i = 0; i < 8; i++) {
            const size_t o = (size_t)(t + i) * D_SZ;
            kk[i] = kp[o]; vv[i] = vp[o];
        }
#pragma unroll
        for (int i = 0; i < 8; i++) {
            const float ek = expf(kk[i]);
            num = fmaf(w, num, ek * vv[i]);
            den = fmaf(w, den, ek);
        }
    }
    g_cn[gid] = num;
    g_cd[gid] = den;
}

__global__ void wkv_p2_kernel(const float* __restrict__ time_decay,
                              const float* __restrict__ x,
                              float* __restrict__ out) {
    const int gid = blockIdx.x * blockDim.x + threadIdx.x;
    const int c = gid & (CH_SZ - 1);
    const int seg = gid >> 14;
    const int d = c & (D_SZ - 1);
    const int b = c >> 11;

    const float e = expf(time_decay[d]);
    const float w = expf(-e);
    const float wl = expf(-(float)SEG_LEN * e);   // w^SEG_LEN

    float num = 0.f, den = 0.f;
    for (int i = 0; i < seg; i++) {
        num = fmaf(wl, num, g_cn[i * CH_SZ + c]);
        den = fmaf(wl, den, g_cd[i * CH_SZ + c]);
    }

    const size_t base = (size_t)b * T_SZ * D_SZ + (size_t)seg * SEG_LEN * D_SZ + d;
    const float* kp = g_k + base;
    const float* vp = g_v + base;
    const float* rp = g_r + base;
    float* op = out + base;

    for (int t = 0; t < SEG_LEN; t += 8) {
        float kk[8], vv[8], rr[8];
#pragma unroll
        for (int i = 0; i < 8; i++) {
            const size_t o = (size_t)(t + i) * D_SZ;
            kk[i] = kp[o]; vv[i] = vp[o]; rr[i] = rp[o];
        }
#pragma unroll
        for (int i = 0; i < 8; i++) {
            const float ek = expf(kk[i]);
            num = fmaf(w, num, ek * vv[i]);
            den = fmaf(w, den, ek);
            op[(size_t)(t + i) * D_SZ] = rr[i] * num / (den + 1e-8f);
        }
    }

    if (seg == 0) {
        float* out2 = out + (size_t)B_SZ * T_SZ * D_SZ;
        out2[c] = x[(size_t)b * T_SZ * D_SZ + (size_t)(T_SZ - 2) * D_SZ + d];
    }
}

// ---------------- launch --------------------------------------------------------
extern "C" void kernel_launch(void* const* d_in, const int* in_sizes, int n_in,
                              void* d_out, int out_size)
{
    const float* x  = (const float*)d_in[0];
    const float* Wk = (const float*)d_in[1];
    const float* Wv = (const float*)d_in[2];
    const float* Wr = (const float*)d_in[3];
    const float* td = (const float*)d_in[4];
    float* out = (float*)d_out;

    cudaFuncSetAttribute(gemm_hmma_kernel,
                         cudaFuncAttributeMaxDynamicSharedMemorySize, GEMM_SMEM);

    convert_x_kernel<<<(M_SZ * (size_t)D_SZ / 4 + 255) / 256, 256>>>(x);
    {
        dim3 g((D_SZ * (size_t)D_SZ / 4 + 255) / 256, 3);
        convert_w_kernel<<<g, 256>>>(Wk, Wv, Wr);
    }

    dim3 gg(D_SZ / BN, M_SZ / BM, 3);   // (16, 128, 3)
    gemm_hmma_kernel<<<gg, 256, GEMM_SMEM>>>();

    const int total = N_SEG * CH_SZ;    // 131072
    wkv_p1_kernel<<<total / 256, 256>>>(td);
    wkv_p2_kernel<<<total / 256, 256>>>(td, x, out);
}

// round 5
// speedup vs baseline: 8.3836x; 1.6504x over previous
#include <cuda_runtime.h>
#include <cuda_fp16.h>
#include <cstdint>

// Problem constants (fixed: B=8, T=2048, D=2048)
#define B_SZ 8
#define T_SZ 2048
#define D_SZ 2048
#define M_SZ (B_SZ * T_SZ)        // 16384
#define CH_SZ (B_SZ * D_SZ)       // 16384 channels
#define SEG_LEN 256
#define N_SEG (T_SZ / SEG_LEN)    // 8

// ---------------- device scratch (static: no runtime allocation) ------------
__device__ __half g_xh[(size_t)M_SZ * D_SZ];     // fp16(x)
__device__ __half g_wh[(size_t)3 * D_SZ * D_SZ]; // fp16(W) for Wk,Wv,Wr
__device__ float g_k[(size_t)M_SZ * D_SZ];
__device__ float g_v[(size_t)M_SZ * D_SZ];
__device__ float g_r[(size_t)M_SZ * D_SZ];
__device__ float g_cn[(size_t)N_SEG * CH_SZ];
__device__ float g_cd[(size_t)N_SEG * CH_SZ];

// ---------------- helpers -----------------------------------------------------
__device__ __forceinline__ uint32_t smem_u32(const void* p) {
    uint32_t a;
    asm("{ .reg .u64 t; cvta.to.shared.u64 t, %1; cvt.u32.u64 %0, t; }" : "=r"(a) : "l"(p));
    return a;
}
__device__ __forceinline__ void cp16(uint32_t dst, const void* src) {
    asm volatile("cp.async.cg.shared.global [%0], [%1], 16;" :: "r"(dst), "l"(src));
}
// zfill variant: src_sz = 0 -> write 16 zero bytes
__device__ __forceinline__ void cp16z(uint32_t dst, const void* src, uint32_t src_sz) {
    asm volatile("cp.async.cg.shared.global [%0], [%1], 16, %2;"
                 :: "r"(dst), "l"(src), "r"(src_sz));
}
#define SWZ128(o) ((o) ^ (((o) >> 3) & 0x70))

__device__ __forceinline__ void ldsm_x4(uint32_t* r, uint32_t addr) {
    asm volatile("ldmatrix.sync.aligned.m8n8.x4.shared.b16 {%0,%1,%2,%3}, [%4];"
                 : "=r"(r[0]), "=r"(r[1]), "=r"(r[2]), "=r"(r[3]) : "r"(addr));
}
__device__ __forceinline__ void mma16816(float* c, const uint32_t* a, const uint32_t* b) {
    asm volatile(
        "mma.sync.aligned.m16n8k16.row.col.f32.f16.f16.f32 "
        "{%0,%1,%2,%3}, {%4,%5,%6,%7}, {%8,%9}, {%0,%1,%2,%3};"
        : "+f"(c[0]), "+f"(c[1]), "+f"(c[2]), "+f"(c[3])
        : "r"(a[0]), "r"(a[1]), "r"(a[2]), "r"(a[3]), "r"(b[0]), "r"(b[1]));
}

// ---------------- conversion: fp32 -> fp16 -------------------------------------
__global__ void convert_x_kernel(const float* __restrict__ x) {
    size_t i4 = (size_t)blockIdx.x * blockDim.x + threadIdx.x;
    if (i4 >= (size_t)M_SZ * D_SZ / 4) return;
    size_t i = i4 * 4;
    float4 v = *(const float4*)(x + i);
    __half2* hp = (__half2*)(g_xh + i);
    hp[0] = __halves2half2(__float2half_rn(v.x), __float2half_rn(v.y));
    hp[1] = __halves2half2(__float2half_rn(v.z), __float2half_rn(v.w));
}

__global__ void convert_w_kernel(const float* __restrict__ Wk,
                                 const float* __restrict__ Wv,
                                 const float* __restrict__ Wr) {
    const int z = blockIdx.y;
    const float* W = (z == 0) ? Wk : (z == 1) ? Wv : Wr;
    size_t i4 = (size_t)blockIdx.x * blockDim.x + threadIdx.x;
    if (i4 >= (size_t)D_SZ * D_SZ / 4) return;
    size_t i = i4 * 4;
    float4 v = *(const float4*)(W + i);
    __half2* op = (__half2*)(g_wh + (size_t)z * D_SZ * D_SZ + i);
    op[0] = __halves2half2(__float2half_rn(v.x), __float2half_rn(v.y));
    op[1] = __halves2half2(__float2half_rn(v.z), __float2half_rn(v.w));
}

// ---------------- HMMA GEMM: C[m,n] = sum_k A[m,k]*W[n,k] ---------------------
// Single fp16 MMA pass. Time shift read-side (zfill at t==0).
// Tile 128x128, BK=64, 3-stage cp.async pipeline, 2 CTA/SM.
#define BM 128
#define BN 128
#define BK 64
#define N_CHUNK (D_SZ / BK)        // 32
#define TILE_B 16384               // 128 rows x 128B
#define STAGE_BYTES (2 * TILE_B)   // A, B
#define N_STAGE 3
#define GEMM_SMEM (N_STAGE * STAGE_BYTES)   // 96 KB

__global__ __launch_bounds__(256, 2)
void gemm_hmma_kernel() {
    extern __shared__ char smem[];
    const uint32_t sbase = smem_u32(smem);
    const int tid = threadIdx.x;
    const int wid = tid >> 5;
    const int lane = tid & 31;
    const int wm = wid & 1;          // 2 warps over M
    const int wn = wid >> 1;         // 4 warps over N

    const int z = blockIdx.z;
    const int m0 = blockIdx.y * BM;
    const int n0 = blockIdx.x * BN;
    const bool shift = (z < 2);

    const __half* B_h = g_wh + (size_t)z * D_SZ * D_SZ;
    float* C = (z == 0) ? g_k : (z == 1) ? g_v : g_r;

    float acc[4][4][4];
#pragma unroll
    for (int i = 0; i < 4; i++)
#pragma unroll
        for (int j = 0; j < 4; j++)
#pragma unroll
            for (int q = 0; q < 4; q++) acc[i][j][q] = 0.f;

    // stage loader: K-chunk c into stage s
    auto load_stage = [&](int c, int s) {
        const int kt = c * BK;
        const uint32_t st = sbase + s * STAGE_BYTES;
#pragma unroll
        for (int it = 0; it < 4; it++) {
            const int i = tid + it * 256;
            const int row = i >> 3, seg = i & 7;
            const uint32_t sw = SWZ128((uint32_t)(row * 128 + seg * 16));
            // A (time shift handled here; zero row at t==0)
            const int rm = m0 + row;
            uint32_t sz = 16;
            int srow = rm;
            if (shift) {
                if ((rm & (T_SZ - 1)) == 0) sz = 0;
                else srow = rm - 1;
            }
            cp16z(st + sw, g_xh + (size_t)srow * D_SZ + kt + seg * 8, sz);
            // B
            cp16(st + TILE_B + sw, B_h + (size_t)(n0 + row) * D_SZ + kt + seg * 8);
        }
        asm volatile("cp.async.commit_group;" ::: "memory");
    };

    load_stage(0, 0);
    load_stage(1, 1);
    load_stage(2, 2);

    const int a_row = lane & 15;
    const int a_half = lane >> 4;
    const int b_nr = (lane & 7) + ((lane >> 4) << 3);
    const int b_half = (lane >> 3) & 1;

    int s = 0;
    for (int c = 0; c < N_CHUNK; c++) {
        if (c < N_CHUNK - 2)      asm volatile("cp.async.wait_group 2;" ::: "memory");
        else if (c == N_CHUNK - 2) asm volatile("cp.async.wait_group 1;" ::: "memory");
        else                       asm volatile("cp.async.wait_group 0;" ::: "memory");
        __syncthreads();

        const uint32_t sA = sbase + s * STAGE_BYTES;
        const uint32_t sB = sA + TILE_B;

#pragma unroll
        for (int ks = 0; ks < 4; ks++) {
            uint32_t aa[4][4], bb[2][4];
#pragma unroll
            for (int mi = 0; mi < 4; mi++) {
                const uint32_t off = SWZ128(
                    (uint32_t)((wm * 64 + mi * 16 + a_row) * 128 + ks * 32 + a_half * 16));
                ldsm_x4(aa[mi], sA + off);
            }
#pragma unroll
            for (int j = 0; j < 2; j++) {
                const uint32_t off = SWZ128(
                    (uint32_t)((wn * 32 + j * 16 + b_nr) * 128 + ks * 32 + b_half * 16));
                ldsm_x4(bb[j], sB + off);
            }
#pragma unroll
            for (int mi = 0; mi < 4; mi++)
#pragma unroll
                for (int ni = 0; ni < 4; ni++)
                    mma16816(acc[mi][ni], aa[mi], &bb[ni >> 1][(ni & 1) * 2]);
        }
        __syncthreads();
        if (c + N_STAGE < N_CHUNK) load_stage(c + N_STAGE, s);
        s = (s == N_STAGE - 1) ? 0 : s + 1;
    }

    // epilogue
#pragma unroll
    for (int mi = 0; mi < 4; mi++) {
        const int gm = m0 + wm * 64 + mi * 16 + (lane >> 2);
#pragma unroll
        for (int ni = 0; ni < 4; ni++) {
            const int gn = n0 + wn * 32 + ni * 8 + (lane & 3) * 2;
            float* p0 = C + (size_t)gm * D_SZ + gn;
            float* p1 = p0 + 8 * D_SZ;
            *(float2*)p0 = make_float2(acc[mi][ni][0], acc[mi][ni][1]);
            *(float2*)p1 = make_float2(acc[mi][ni][2], acc[mi][ni][3]);
        }
    }
}

// ---------------- split WKV scan ------------------------------------------------
__global__ void wkv_p1_kernel(const float* __restrict__ time_decay) {
    const int gid = blockIdx.x * blockDim.x + threadIdx.x;
    const int c = gid & (CH_SZ - 1);
    const int seg = gid >> 14;
    const int d = c & (D_SZ - 1);
    const int b = c >> 11;
    const float w = expf(-expf(time_decay[d]));

    const size_t base = (size_t)b * T_SZ * D_SZ + (size_t)seg * SEG_LEN * D_SZ + d;
    const float* kp = g_k + base;
    const float* vp = g_v + base;

    float num = 0.f, den = 0.f;
    for (int t = 0; t < SEG_LEN; t += 8) {
        float kk[8], vv[8];
#pragma unroll
        for (int i = 0; i < 8; i++) {
            const size_t o = (size_t)(t + i) * D_SZ;
            kk[i] = kp[o]; vv[i] = vp[o];
        }
#pragma unroll
        for (int i = 0; i < 8; i++) {
            const float ek = expf(kk[i]);
            num = fmaf(w, num, ek * vv[i]);
            den = fmaf(w, den, ek);
        }
    }
    g_cn[gid] = num;
    g_cd[gid] = den;
}

__global__ void wkv_p2_kernel(const float* __restrict__ time_decay,
                              const float* __restrict__ x,
                              float* __restrict__ out) {
    const int gid = blockIdx.x * blockDim.x + threadIdx.x;
    const int c = gid & (CH_SZ - 1);
    const int seg = gid >> 14;
    const int d = c & (D_SZ - 1);
    const int b = c >> 11;

    const float e = expf(time_decay[d]);
    const float w = expf(-e);
    const float wl = expf(-(float)SEG_LEN * e);   // w^SEG_LEN

    float num = 0.f, den = 0.f;
    for (int i = 0; i < seg; i++) {
        num = fmaf(wl, num, g_cn[i * CH_SZ + c]);
        den = fmaf(wl, den, g_cd[i * CH_SZ + c]);
    }

    const size_t base = (size_t)b * T_SZ * D_SZ + (size_t)seg * SEG_LEN * D_SZ + d;
    const float* kp = g_k + base;
    const float* vp = g_v + base;
    const float* rp = g_r + base;
    float* op = out + base;

    for (int t = 0; t < SEG_LEN; t += 8) {
        float kk[8], vv[8], rr[8];
#pragma unroll
        for (int i = 0; i < 8; i++) {
            const size_t o = (size_t)(t + i) * D_SZ;
            kk[i] = kp[o]; vv[i] = vp[o]; rr[i] = rp[o];
        }
#pragma unroll
        for (int i = 0; i < 8; i++) {
            const float ek = expf(kk[i]);
            num = fmaf(w, num, ek * vv[i]);
            den = fmaf(w, den, ek);
            op[(size_t)(t + i) * D_SZ] = rr[i] * num / (den + 1e-8f);
        }
    }

    if (seg == 0) {
        float* out2 = out + (size_t)B_SZ * T_SZ * D_SZ;
        out2[c] = x[(size_t)b * T_SZ * D_SZ + (size_t)(T_SZ - 2) * D_SZ + d];
    }
}

// ---------------- launch --------------------------------------------------------
extern "C" void kernel_launch(void* const* d_in, const int* in_sizes, int n_in,
                              void* d_out, int out_size)
{
    const float* x  = (const float*)d_in[0];
    const float* Wk = (const float*)d_in[1];
    const float* Wv = (const float*)d_in[2];
    const float* Wr = (const float*)d_in[3];
    const float* td = (const float*)d_in[4];
    float* out = (float*)d_out;

    cudaFuncSetAttribute(gemm_hmma_kernel,
                         cudaFuncAttributeMaxDynamicSharedMemorySize, GEMM_SMEM);

    convert_x_kernel<<<(M_SZ * (size_t)D_SZ / 4 + 255) / 256, 256>>>(x);
    {
        dim3 g((D_SZ * (size_t)D_SZ / 4 + 255) / 256, 3);
        convert_w_kernel<<<g, 256>>>(Wk, Wv, Wr);
    }

    dim3 gg(D_SZ / BN, M_SZ / BM, 3);   // (16, 128, 3)
    gemm_hmma_kernel<<<gg, 256, GEMM_SMEM>>>();

    const int total = N_SEG * CH_SZ;    // 131072
    wkv_p1_kernel<<<total / 256, 256>>>(td);
    wkv_p2_kernel<<<total / 256, 256>>>(td, x, out);
}